// round 13
// baseline (speedup 1.0000x reference)
#include <cuda_runtime.h>
#include <math.h>

#define DD 31
#define DIMV 32
#define TSTRIDE 36   // floats per s_T row in K1 shared (32 data + 4 pad)
#define MARGIN 0.85f
#define MAXB 2048
#define SCR_STRIDE 1092  // per-b scratch floats: 1024 T + 32 (-th) + 1 tbh + pad (16B-aligned)

__device__ float g_scr[MAXB * SCR_STRIDE];

__device__ __forceinline__ float gelu_exact(float x) {
    return 0.5f * x * (1.0f + erff(x * 0.70710678118654752440f));
}

__device__ __forceinline__ float warp_sum(float v) {
#pragma unroll
    for (int o = 16; o; o >>= 1) v += __shfl_xor_sync(0xffffffffu, v, o);
    return v;
}

// ============================================================================
// K1: per-row prologue — build fused rot+boost matrix T, transformed head, bias
// ============================================================================
__global__ __launch_bounds__(128, 4)
void build_kernel(const int* __restrict__ g_u, const int* __restrict__ g_r,
                  const float* __restrict__ emb, const float* __restrict__ bias_head,
                  const float* __restrict__ head_rot_w, const float* __restrict__ head_boost_w,
                  const float* __restrict__ tail_rot_w, const float* __restrict__ tail_boost_w) {
    __shared__ __align__(16) float s_wt[DD][DIMV];      // gelu'd tail Householder rows; col31 = 0
    __shared__ __align__(16) float s_wh[DD][DIMV];      // gelu'd head rows; [i][31] = 2/n2
    __shared__ __align__(16) float s_T[DIMV][TSTRIDE];  // fused matrix, row = input dim
    __shared__ __align__(16) float s_th[DIMV];          // transformed head vector
    __shared__ __align__(16) float s_ro[DIMV];          // tail rapidity + pad 0
    __shared__ float s_beta[DD];                        // -2/n2 per tail reflection
    __shared__ float s_par[4];                          // zeta_t, kappa_t, tanh(bias_head[u])

    const int b    = blockIdx.x;
    const int tid  = threadIdx.x;
    const int lane = tid & 31;
    const int wid  = tid >> 5;   // 0..3
    const int rb   = g_r[b];

    // Phase A: gelu both rotation tables
    const float* tw = tail_rot_w + (long)rb * (DD * DD);
    const float* hw = head_rot_w + (long)rb * (DD * DD);
    for (int k = tid; k < DD * DIMV; k += 128) {
        int i = k >> 5, j = k & 31;
        s_wt[i][j] = (j < DD) ? gelu_exact(tw[i * DD + j]) : 0.f;
        s_wh[i][j] = (j < DD) ? gelu_exact(hw[i * DD + j]) : 0.f;
    }
    __syncthreads();

    // Phase A2 (4 warps): boost params / norms / head bias
    if (wid == 0) {
        float ro = (lane < DD) ? tanhf(tail_boost_w[(long)rb * DD + lane]) * (1.0f / DIMV) : 0.f;
        s_ro[lane] = ro;
        float v2 = warp_sum(ro * ro);
        if (lane == 0) {
            float zeta = 1.0f / (sqrtf(1.0f - v2) + 1e-8f);
            s_par[0] = zeta;
            s_par[1] = (zeta - 1.0f) / (v2 + 1e-9f);
        }
    } else if (wid == 1) {
#pragma unroll 1
        for (int i = 0; i < DD; i++) {
            float w  = (lane < DD) ? s_wt[i][lane] : 0.f;
            float n2 = warp_sum(w * w);
            if (lane == 0) s_beta[i] = -2.0f / n2;
        }
    } else if (wid == 2) {
#pragma unroll 1
        for (int i = 0; i < DD; i++) {
            float w  = (lane < DD) ? s_wh[i][lane] : 0.f;
            float n2 = warp_sum(w * w);
            if (lane == 0) s_wh[i][DD] = 2.0f / n2;
        }
    } else {
        if (lane == 0) s_par[2] = tanhf(bias_head[g_u[b]]);
    }
    __syncthreads();

    // Build (warp 0): lane owns column `lane` of P = H31..H1 (= row `lane` of Q)
    if (wid == 0) {
        const float zt = s_par[0];
        const float kp = s_par[1];
        if (lane < DD) {
            float P[DIMV];
#pragma unroll
            for (int k = 0; k < DIMV; k++) P[k] = (k == lane) ? 1.f : 0.f;

#pragma unroll 1
            for (int i = 0; i < DD; i++) {
                float z0 = 0.f, z1 = 0.f, z2 = 0.f, z3 = 0.f;
#pragma unroll
                for (int k = 0; k < DIMV; k += 4) {
                    z0 = fmaf(s_wt[i][k],     P[k],     z0);
                    z1 = fmaf(s_wt[i][k + 1], P[k + 1], z1);
                    z2 = fmaf(s_wt[i][k + 2], P[k + 2], z2);
                    z3 = fmaf(s_wt[i][k + 3], P[k + 3], z3);
                }
                const float g = s_beta[i] * ((z0 + z1) + (z2 + z3));
#pragma unroll
                for (int k = 0; k < DIMV; k++) P[k] = fmaf(g, s_wt[i][k], P[k]);
            }
            float s0 = 0.f, s1 = 0.f, s2 = 0.f, s3 = 0.f;
#pragma unroll
            for (int k = 0; k < DIMV; k += 4) {
                s0 = fmaf(s_ro[k],     P[k],     s0);
                s1 = fmaf(s_ro[k + 1], P[k + 1], s1);
                s2 = fmaf(s_ro[k + 2], P[k + 2], s2);
                s3 = fmaf(s_ro[k + 3], P[k + 3], s3);
            }
            const float s  = (s0 + s1) + (s2 + s3);
            const float ks = kp * s;
            float* row = &s_T[lane + 1][0];
            row[0] = -zt * s;
#pragma unroll
            for (int m = 0; m < DD; m++) row[1 + m] = fmaf(ks, s_ro[m], P[m]);
        } else {
            float* row = &s_T[0][0];
            row[0] = zt;
#pragma unroll
            for (int j = 0; j < DD; j++) row[1 + j] = -zt * s_ro[j];
        }
    }
    // Head chain (warp 1, concurrent with build)
    else if (wid == 1) {
        float c = emb[(long)g_u[b] * DIMV + lane];
#pragma unroll 1
        for (int i = 0; i < DD; i++) {
            float w   = (lane >= 1) ? s_wh[i][lane - 1] : 0.f;
            float sc  = s_wh[i][DD];
            float dot = warp_sum(c * w);
            c = fmaf(-sc * dot, w, c);
        }
        float rh   = (lane >= 1) ? tanhf(head_boost_w[(long)rb * DD + lane - 1]) * (1.0f / DIMV) : 0.f;
        float v2   = warp_sum(rh * rh);
        float zeta = 1.0f / (sqrtf(1.0f - v2) + 1e-8f);
        float coef = (zeta - 1.0f) / (v2 + 1e-9f);
        float tval = __shfl_sync(0xffffffffu, c, 0);
        float dotb = warp_sum(c * rh);
        float res;
        if (lane == 0) res = zeta * tval - zeta * dotb;
        else           res = -zeta * tval * rh + c + coef * rh * dotb;
        s_th[lane] = res;
    }
    __syncthreads();

    // Export to global scratch (coalesced)
    float* dst = g_scr + (long)b * SCR_STRIDE;
    for (int k = tid; k < DIMV * DIMV; k += 128)
        dst[k] = s_T[k >> 5][k & 31];
    if (tid < DIMV) dst[DIMV * DIMV + tid] = -s_th[tid];
    if (tid == 0)   dst[DIMV * DIMV + DIMV] = s_par[2];
}

// ============================================================================
// K2: high-occupancy matvec — one tail vector per thread
// ============================================================================
__global__ __launch_bounds__(256, 3)
void matvec_kernel(const int* __restrict__ g_v, const float* __restrict__ emb,
                   const float* __restrict__ bias_tail, float* __restrict__ out, int N) {
    __shared__ __align__(16) float sT[DIMV * DIMV];  // T row-major [input d][output c]
    __shared__ __align__(16) float snth[DIMV];       // -th
    __shared__ float stbh;

    const int b   = blockIdx.x;
    const int tid = threadIdx.x;

    const float* src = g_scr + (long)b * SCR_STRIDE;
    if (tid < 256) ((float4*)sT)[tid] = ((const float4*)src)[tid];
    if (tid < 8)   ((float4*)snth)[tid] = ((const float4*)src)[256 + tid];
    if (tid == 0)  stbh = src[DIMV * DIMV + DIMV];
    __syncthreads();

    const float tbh = stbh;

    for (int n = tid; n < N; n += blockDim.x) {
        const int vi = g_v[(long)b * N + n];
        const float4* ep = (const float4*)(emb + (long)vi * DIMV);
        const float btail = bias_tail[vi];

        float y[DIMV];
#pragma unroll
        for (int c = 0; c < DIMV; c++) y[c] = snth[c];   // already negated head

#pragma unroll
        for (int q = 0; q < 8; q++) {
            const float4 x4 = ep[q];
#pragma unroll
            for (int r = 0; r < 4; r++) {
                const float x = (r == 0) ? x4.x : (r == 1) ? x4.y : (r == 2) ? x4.z : x4.w;
                const float* row = &sT[(4 * q + r) * DIMV];
#pragma unroll
                for (int c = 0; c < DIMV; c++)
                    y[c] = fmaf(x, row[c], y[c]);
            }
        }

        float a0 = 0.f, a1 = 0.f, a2 = 0.f, a3 = 0.f;
#pragma unroll
        for (int c = 0; c < DIMV; c += 4) {
            a0 = fmaf(y[c],     y[c],     a0);
            a1 = fmaf(y[c + 1], y[c + 1], a1);
            a2 = fmaf(y[c + 2], y[c + 2], a2);
            a3 = fmaf(y[c + 3], y[c + 3], a3);
        }
        const float acc = (a0 + a1) + (a2 + a3);
        const float mkv = acc - 2.f * y[0] * y[0];

        out[(long)b * N + n] = MARGIN - mkv + tbh + tanhf(btail);
    }
}

extern "C" void kernel_launch(void* const* d_in, const int* in_sizes, int n_in,
                              void* d_out, int out_size) {
    const int*   u   = (const int*)d_in[0];
    const int*   r   = (const int*)d_in[1];
    const int*   v   = (const int*)d_in[2];
    const float* emb = (const float*)d_in[3];
    const float* bh  = (const float*)d_in[4];
    const float* bt  = (const float*)d_in[5];
    const float* hrw = (const float*)d_in[6];
    const float* hbw = (const float*)d_in[7];
    const float* trw = (const float*)d_in[8];
    const float* tbw = (const float*)d_in[9];
    float* out = (float*)d_out;

    const int B = in_sizes[0];
    const int N = in_sizes[2] / B;

    build_kernel<<<B, 128>>>(u, r, emb, bh, hrw, hbw, trw, tbw);
    matvec_kernel<<<B, 256>>>(v, emb, bt, out, N);
}

// round 14
// speedup vs baseline: 1.0362x; 1.0362x over previous
#include <cuda_runtime.h>
#include <math.h>

#define DD 31
#define DIMV 32
#define TSTRIDE 36   // floats per s_T row in K1 shared (32 data + 4 pad)
#define MARGIN 0.85f
#define MAXB 2048
#define SCR_STRIDE 1092  // per-b scratch floats: 1024 T + 32 (-th) + 1 tbh + pad (16B-aligned)

__device__ float g_scr[MAXB * SCR_STRIDE];

__device__ __forceinline__ float gelu_exact(float x) {
    return 0.5f * x * (1.0f + erff(x * 0.70710678118654752440f));
}

__device__ __forceinline__ float warp_sum(float v) {
#pragma unroll
    for (int o = 16; o; o >>= 1) v += __shfl_xor_sync(0xffffffffu, v, o);
    return v;
}

// ============================================================================
// K1: per-row prologue — build fused rot+boost matrix T, transformed head, bias
// ============================================================================
__global__ __launch_bounds__(128, 4)
void build_kernel(const int* __restrict__ g_u, const int* __restrict__ g_r,
                  const float* __restrict__ emb, const float* __restrict__ bias_head,
                  const float* __restrict__ head_rot_w, const float* __restrict__ head_boost_w,
                  const float* __restrict__ tail_rot_w, const float* __restrict__ tail_boost_w) {
    __shared__ __align__(16) float s_wt[DD][DIMV];      // gelu'd tail Householder rows; col31 = 0
    __shared__ __align__(16) float s_wh[DD][DIMV];      // gelu'd head rows; [i][31] = 2/n2
    __shared__ __align__(16) float s_T[DIMV][TSTRIDE];  // fused matrix, row = input dim
    __shared__ __align__(16) float s_th[DIMV];          // transformed head vector
    __shared__ __align__(16) float s_ro[DIMV];          // tail rapidity + pad 0
    __shared__ float s_beta[DD];                        // -2/n2 per tail reflection
    __shared__ float s_par[4];                          // zeta_t, kappa_t, tanh(bias_head[u])

    const int b    = blockIdx.x;
    const int tid  = threadIdx.x;
    const int lane = tid & 31;
    const int wid  = tid >> 5;   // 0..3
    const int rb   = g_r[b];

    // Phase A: gelu both rotation tables
    const float* tw = tail_rot_w + (long)rb * (DD * DD);
    const float* hw = head_rot_w + (long)rb * (DD * DD);
    for (int k = tid; k < DD * DIMV; k += 128) {
        int i = k >> 5, j = k & 31;
        s_wt[i][j] = (j < DD) ? gelu_exact(tw[i * DD + j]) : 0.f;
        s_wh[i][j] = (j < DD) ? gelu_exact(hw[i * DD + j]) : 0.f;
    }
    __syncthreads();

    // Phase A2 (4 warps): boost params / norms / head bias
    if (wid == 0) {
        float ro = (lane < DD) ? tanhf(tail_boost_w[(long)rb * DD + lane]) * (1.0f / DIMV) : 0.f;
        s_ro[lane] = ro;
        float v2 = warp_sum(ro * ro);
        if (lane == 0) {
            float zeta = 1.0f / (sqrtf(1.0f - v2) + 1e-8f);
            s_par[0] = zeta;
            s_par[1] = (zeta - 1.0f) / (v2 + 1e-9f);
        }
    } else if (wid == 1) {
#pragma unroll 1
        for (int i = 0; i < DD; i++) {
            float w  = (lane < DD) ? s_wt[i][lane] : 0.f;
            float n2 = warp_sum(w * w);
            if (lane == 0) s_beta[i] = -2.0f / n2;
        }
    } else if (wid == 2) {
#pragma unroll 1
        for (int i = 0; i < DD; i++) {
            float w  = (lane < DD) ? s_wh[i][lane] : 0.f;
            float n2 = warp_sum(w * w);
            if (lane == 0) s_wh[i][DD] = 2.0f / n2;
        }
    } else {
        if (lane == 0) s_par[2] = tanhf(bias_head[g_u[b]]);
    }
    __syncthreads();

    // Build (warp 0): lane owns column `lane` of P = H31..H1 (= row `lane` of Q)
    if (wid == 0) {
        const float zt = s_par[0];
        const float kp = s_par[1];
        if (lane < DD) {
            float P[DIMV];
#pragma unroll
            for (int k = 0; k < DIMV; k++) P[k] = (k == lane) ? 1.f : 0.f;

#pragma unroll 1
            for (int i = 0; i < DD; i++) {
                float z0 = 0.f, z1 = 0.f, z2 = 0.f, z3 = 0.f;
#pragma unroll
                for (int k = 0; k < DIMV; k += 4) {
                    z0 = fmaf(s_wt[i][k],     P[k],     z0);
                    z1 = fmaf(s_wt[i][k + 1], P[k + 1], z1);
                    z2 = fmaf(s_wt[i][k + 2], P[k + 2], z2);
                    z3 = fmaf(s_wt[i][k + 3], P[k + 3], z3);
                }
                const float g = s_beta[i] * ((z0 + z1) + (z2 + z3));
#pragma unroll
                for (int k = 0; k < DIMV; k++) P[k] = fmaf(g, s_wt[i][k], P[k]);
            }
            float s0 = 0.f, s1 = 0.f, s2 = 0.f, s3 = 0.f;
#pragma unroll
            for (int k = 0; k < DIMV; k += 4) {
                s0 = fmaf(s_ro[k],     P[k],     s0);
                s1 = fmaf(s_ro[k + 1], P[k + 1], s1);
                s2 = fmaf(s_ro[k + 2], P[k + 2], s2);
                s3 = fmaf(s_ro[k + 3], P[k + 3], s3);
            }
            const float s  = (s0 + s1) + (s2 + s3);
            const float ks = kp * s;
            float* row = &s_T[lane + 1][0];
            row[0] = -zt * s;
#pragma unroll
            for (int m = 0; m < DD; m++) row[1 + m] = fmaf(ks, s_ro[m], P[m]);
        } else {
            float* row = &s_T[0][0];
            row[0] = zt;
#pragma unroll
            for (int j = 0; j < DD; j++) row[1 + j] = -zt * s_ro[j];
        }
    }
    // Head chain (warp 1, concurrent with build)
    else if (wid == 1) {
        float c = emb[(long)g_u[b] * DIMV + lane];
#pragma unroll 1
        for (int i = 0; i < DD; i++) {
            float w   = (lane >= 1) ? s_wh[i][lane - 1] : 0.f;
            float sc  = s_wh[i][DD];
            float dot = warp_sum(c * w);
            c = fmaf(-sc * dot, w, c);
        }
        float rh   = (lane >= 1) ? tanhf(head_boost_w[(long)rb * DD + lane - 1]) * (1.0f / DIMV) : 0.f;
        float v2   = warp_sum(rh * rh);
        float zeta = 1.0f / (sqrtf(1.0f - v2) + 1e-8f);
        float coef = (zeta - 1.0f) / (v2 + 1e-9f);
        float tval = __shfl_sync(0xffffffffu, c, 0);
        float dotb = warp_sum(c * rh);
        float res;
        if (lane == 0) res = zeta * tval - zeta * dotb;
        else           res = -zeta * tval * rh + c + coef * rh * dotb;
        s_th[lane] = res;
    }
    __syncthreads();

    // Export to global scratch (coalesced)
    float* dst = g_scr + (long)b * SCR_STRIDE;
    for (int k = tid; k < DIMV * DIMV; k += 128)
        dst[k] = s_T[k >> 5][k & 31];
    if (tid < DIMV) dst[DIMV * DIMV + tid] = -s_th[tid];
    if (tid == 0)   dst[DIMV * DIMV + DIMV] = s_par[2];
}

// ============================================================================
// K2: matvec — one tail vector per thread, 128-reg budget (NO smaller cap!)
// ============================================================================
__global__ __launch_bounds__(256, 2)
void matvec_kernel(const int* __restrict__ g_v, const float* __restrict__ emb,
                   const float* __restrict__ bias_tail, float* __restrict__ out, int N) {
    __shared__ __align__(16) float sT[DIMV * DIMV];  // T row-major [input d][output c]
    __shared__ __align__(16) float snth[DIMV];       // -th
    __shared__ float stbh;

    const int b   = blockIdx.x;
    const int tid = threadIdx.x;

    const float* src = g_scr + (long)b * SCR_STRIDE;
    if (tid < 256) ((float4*)sT)[tid] = ((const float4*)src)[tid];
    if (tid < 8)   ((float4*)snth)[tid] = ((const float4*)src)[256 + tid];
    if (tid == 0)  stbh = src[DIMV * DIMV + DIMV];
    __syncthreads();

    const float tbh = stbh;

    for (int n = tid; n < N; n += blockDim.x) {
        const int vi = g_v[(long)b * N + n];
        const float4* ep = (const float4*)(emb + (long)vi * DIMV);
        const float btail = bias_tail[vi];

        float y[DIMV];
#pragma unroll
        for (int c = 0; c < DIMV; c++) y[c] = snth[c];   // already negated head

#pragma unroll
        for (int q = 0; q < 8; q++) {
            const float4 x4 = ep[q];
#pragma unroll
            for (int r = 0; r < 4; r++) {
                const float x = (r == 0) ? x4.x : (r == 1) ? x4.y : (r == 2) ? x4.z : x4.w;
                const float* row = &sT[(4 * q + r) * DIMV];
#pragma unroll
                for (int c = 0; c < DIMV; c++)
                    y[c] = fmaf(x, row[c], y[c]);
            }
        }

        float a0 = 0.f, a1 = 0.f, a2 = 0.f, a3 = 0.f;
#pragma unroll
        for (int c = 0; c < DIMV; c += 4) {
            a0 = fmaf(y[c],     y[c],     a0);
            a1 = fmaf(y[c + 1], y[c + 1], a1);
            a2 = fmaf(y[c + 2], y[c + 2], a2);
            a3 = fmaf(y[c + 3], y[c + 3], a3);
        }
        const float acc = (a0 + a1) + (a2 + a3);
        const float mkv = acc - 2.f * y[0] * y[0];

        out[(long)b * N + n] = MARGIN - mkv + tbh + tanhf(btail);
    }
}

extern "C" void kernel_launch(void* const* d_in, const int* in_sizes, int n_in,
                              void* d_out, int out_size) {
    const int*   u   = (const int*)d_in[0];
    const int*   r   = (const int*)d_in[1];
    const int*   v   = (const int*)d_in[2];
    const float* emb = (const float*)d_in[3];
    const float* bh  = (const float*)d_in[4];
    const float* bt  = (const float*)d_in[5];
    const float* hrw = (const float*)d_in[6];
    const float* hbw = (const float*)d_in[7];
    const float* trw = (const float*)d_in[8];
    const float* tbw = (const float*)d_in[9];
    float* out = (float*)d_out;

    const int B = in_sizes[0];
    const int N = in_sizes[2] / B;

    build_kernel<<<B, 128>>>(u, r, emb, bh, hrw, hbw, trw, tbw);
    matvec_kernel<<<B, 256>>>(v, emb, bt, out, N);
}

// round 15
// speedup vs baseline: 6.5390x; 6.3107x over previous
#include <cuda_runtime.h>
#include <math.h>

#define DD 31
#define DIMV 32
#define TSTRIDE 36   // floats per s_T row in K1 shared (32 data + 4 pad)
#define MARGIN 0.85f
#define MAXB 2048
#define SCR_STRIDE 1092  // per-b scratch floats: 1024 T + 32 (-th) + 1 tbh + pad (16B-aligned)

__device__ float g_scr[MAXB * SCR_STRIDE];

__device__ __forceinline__ float gelu_exact(float x) {
    return 0.5f * x * (1.0f + erff(x * 0.70710678118654752440f));
}

__device__ __forceinline__ float warp_sum(float v) {
#pragma unroll
    for (int o = 16; o; o >>= 1) v += __shfl_xor_sync(0xffffffffu, v, o);
    return v;
}

// ============================================================================
// K1: per-row prologue — build fused rot+boost matrix T, transformed head, bias
// ============================================================================
__global__ __launch_bounds__(128, 4)
void build_kernel(const int* __restrict__ g_u, const int* __restrict__ g_r,
                  const float* __restrict__ emb, const float* __restrict__ bias_head,
                  const float* __restrict__ head_rot_w, const float* __restrict__ head_boost_w,
                  const float* __restrict__ tail_rot_w, const float* __restrict__ tail_boost_w) {
    __shared__ __align__(16) float s_wt[DD][DIMV];      // gelu'd tail Householder rows; col31 = 0
    __shared__ __align__(16) float s_wh[DD][DIMV];      // gelu'd head rows; [i][31] = 2/n2
    __shared__ __align__(16) float s_T[DIMV][TSTRIDE];  // fused matrix, row = input dim
    __shared__ __align__(16) float s_th[DIMV];          // transformed head vector
    __shared__ __align__(16) float s_ro[DIMV];          // tail rapidity + pad 0
    __shared__ float s_beta[DD];                        // -2/n2 per tail reflection
    __shared__ float s_par[4];                          // zeta_t, kappa_t, tanh(bias_head[u])

    const int b    = blockIdx.x;
    const int tid  = threadIdx.x;
    const int lane = tid & 31;
    const int wid  = tid >> 5;   // 0..3
    const int rb   = g_r[b];

    // Phase A: gelu both rotation tables
    const float* tw = tail_rot_w + (long)rb * (DD * DD);
    const float* hw = head_rot_w + (long)rb * (DD * DD);
    for (int k = tid; k < DD * DIMV; k += 128) {
        int i = k >> 5, j = k & 31;
        s_wt[i][j] = (j < DD) ? gelu_exact(tw[i * DD + j]) : 0.f;
        s_wh[i][j] = (j < DD) ? gelu_exact(hw[i * DD + j]) : 0.f;
    }
    __syncthreads();

    // Phase A2 (4 warps): boost params / norms / head bias
    if (wid == 0) {
        float ro = (lane < DD) ? tanhf(tail_boost_w[(long)rb * DD + lane]) * (1.0f / DIMV) : 0.f;
        s_ro[lane] = ro;
        float v2 = warp_sum(ro * ro);
        if (lane == 0) {
            float zeta = 1.0f / (sqrtf(1.0f - v2) + 1e-8f);
            s_par[0] = zeta;
            s_par[1] = (zeta - 1.0f) / (v2 + 1e-9f);
        }
    } else if (wid == 1) {
#pragma unroll 1
        for (int i = 0; i < DD; i++) {
            float w  = (lane < DD) ? s_wt[i][lane] : 0.f;
            float n2 = warp_sum(w * w);
            if (lane == 0) s_beta[i] = -2.0f / n2;
        }
    } else if (wid == 2) {
#pragma unroll 1
        for (int i = 0; i < DD; i++) {
            float w  = (lane < DD) ? s_wh[i][lane] : 0.f;
            float n2 = warp_sum(w * w);
            if (lane == 0) s_wh[i][DD] = 2.0f / n2;
        }
    } else {
        if (lane == 0) s_par[2] = tanhf(bias_head[g_u[b]]);
    }
    __syncthreads();

    // Build (warp 0): lane owns column `lane` of P = H31..H1 (= row `lane` of Q)
    if (wid == 0) {
        const float zt = s_par[0];
        const float kp = s_par[1];
        if (lane < DD) {
            float P[DIMV];
#pragma unroll
            for (int k = 0; k < DIMV; k++) P[k] = (k == lane) ? 1.f : 0.f;

#pragma unroll 1
            for (int i = 0; i < DD; i++) {
                float z0 = 0.f, z1 = 0.f, z2 = 0.f, z3 = 0.f;
#pragma unroll
                for (int k = 0; k < DIMV; k += 4) {
                    z0 = fmaf(s_wt[i][k],     P[k],     z0);
                    z1 = fmaf(s_wt[i][k + 1], P[k + 1], z1);
                    z2 = fmaf(s_wt[i][k + 2], P[k + 2], z2);
                    z3 = fmaf(s_wt[i][k + 3], P[k + 3], z3);
                }
                const float g = s_beta[i] * ((z0 + z1) + (z2 + z3));
#pragma unroll
                for (int k = 0; k < DIMV; k++) P[k] = fmaf(g, s_wt[i][k], P[k]);
            }
            float s0 = 0.f, s1 = 0.f, s2 = 0.f, s3 = 0.f;
#pragma unroll
            for (int k = 0; k < DIMV; k += 4) {
                s0 = fmaf(s_ro[k],     P[k],     s0);
                s1 = fmaf(s_ro[k + 1], P[k + 1], s1);
                s2 = fmaf(s_ro[k + 2], P[k + 2], s2);
                s3 = fmaf(s_ro[k + 3], P[k + 3], s3);
            }
            const float s  = (s0 + s1) + (s2 + s3);
            const float ks = kp * s;
            float* row = &s_T[lane + 1][0];
            row[0] = -zt * s;
#pragma unroll
            for (int m = 0; m < DD; m++) row[1 + m] = fmaf(ks, s_ro[m], P[m]);
        } else {
            float* row = &s_T[0][0];
            row[0] = zt;
#pragma unroll
            for (int j = 0; j < DD; j++) row[1 + j] = -zt * s_ro[j];
        }
    }
    // Head chain (warp 1, concurrent with build)
    else if (wid == 1) {
        float c = emb[(long)g_u[b] * DIMV + lane];
#pragma unroll 1
        for (int i = 0; i < DD; i++) {
            float w   = (lane >= 1) ? s_wh[i][lane - 1] : 0.f;
            float sc  = s_wh[i][DD];
            float dot = warp_sum(c * w);
            c = fmaf(-sc * dot, w, c);
        }
        float rh   = (lane >= 1) ? tanhf(head_boost_w[(long)rb * DD + lane - 1]) * (1.0f / DIMV) : 0.f;
        float v2   = warp_sum(rh * rh);
        float zeta = 1.0f / (sqrtf(1.0f - v2) + 1e-8f);
        float coef = (zeta - 1.0f) / (v2 + 1e-9f);
        float tval = __shfl_sync(0xffffffffu, c, 0);
        float dotb = warp_sum(c * rh);
        float res;
        if (lane == 0) res = zeta * tval - zeta * dotb;
        else           res = -zeta * tval * rh + c + coef * rh * dotb;
        s_th[lane] = res;
    }
    __syncthreads();

    // Export to global scratch (coalesced)
    float* dst = g_scr + (long)b * SCR_STRIDE;
    for (int k = tid; k < DIMV * DIMV; k += 128)
        dst[k] = s_T[k >> 5][k & 31];
    if (tid < DIMV) dst[DIMV * DIMV + tid] = -s_th[tid];
    if (tid == 0)   dst[DIMV * DIMV + DIMV] = s_par[2];
}

// ============================================================================
// K2: matvec — one tail vector per thread; OUTER LOOP NOT UNROLLED so the
//     LDS scheduling window stays small and y[] provably stays in registers.
// ============================================================================
__global__ __launch_bounds__(256, 2)
void matvec_kernel(const int* __restrict__ g_v, const float* __restrict__ emb,
                   const float* __restrict__ bias_tail, float* __restrict__ out, int N) {
    __shared__ __align__(16) float sT[DIMV * DIMV];  // T row-major [input d][output c]
    __shared__ __align__(16) float snth[DIMV];       // -th
    __shared__ float stbh;

    const int b   = blockIdx.x;
    const int tid = threadIdx.x;

    const float* src = g_scr + (long)b * SCR_STRIDE;
    if (tid < 256) ((float4*)sT)[tid] = ((const float4*)src)[tid];
    if (tid < 8)   ((float4*)snth)[tid] = ((const float4*)src)[256 + tid];
    if (tid == 0)  stbh = src[DIMV * DIMV + DIMV];
    __syncthreads();

    const float tbh = stbh;

    for (int n = tid; n < N; n += blockDim.x) {
        const int vi = g_v[(long)b * N + n];
        const float4* ep = (const float4*)(emb + (long)vi * DIMV);
        const float btail = bias_tail[vi];

        float y[DIMV];
#pragma unroll
        for (int c = 0; c < DIMV; c++) y[c] = snth[c];   // already negated head

#pragma unroll 1
        for (int q = 0; q < 8; q++) {
            const float4 x4 = ep[q];
            const float* r0 = &sT[(4 * q + 0) * DIMV];
            const float* r1 = &sT[(4 * q + 1) * DIMV];
            const float* r2 = &sT[(4 * q + 2) * DIMV];
            const float* r3 = &sT[(4 * q + 3) * DIMV];
#pragma unroll
            for (int c = 0; c < DIMV; c++) {
                float t = fmaf(x4.x, r0[c], y[c]);
                t = fmaf(x4.y, r1[c], t);
                t = fmaf(x4.z, r2[c], t);
                y[c] = fmaf(x4.w, r3[c], t);
            }
        }

        float a0 = 0.f, a1 = 0.f, a2 = 0.f, a3 = 0.f;
#pragma unroll
        for (int c = 0; c < DIMV; c += 4) {
            a0 = fmaf(y[c],     y[c],     a0);
            a1 = fmaf(y[c + 1], y[c + 1], a1);
            a2 = fmaf(y[c + 2], y[c + 2], a2);
            a3 = fmaf(y[c + 3], y[c + 3], a3);
        }
        const float acc = (a0 + a1) + (a2 + a3);
        const float mkv = acc - 2.f * y[0] * y[0];

        out[(long)b * N + n] = MARGIN - mkv + tbh + tanhf(btail);
    }
}

extern "C" void kernel_launch(void* const* d_in, const int* in_sizes, int n_in,
                              void* d_out, int out_size) {
    const int*   u   = (const int*)d_in[0];
    const int*   r   = (const int*)d_in[1];
    const int*   v   = (const int*)d_in[2];
    const float* emb = (const float*)d_in[3];
    const float* bh  = (const float*)d_in[4];
    const float* bt  = (const float*)d_in[5];
    const float* hrw = (const float*)d_in[6];
    const float* hbw = (const float*)d_in[7];
    const float* trw = (const float*)d_in[8];
    const float* tbw = (const float*)d_in[9];
    float* out = (float*)d_out;

    const int B = in_sizes[0];
    const int N = in_sizes[2] / B;

    build_kernel<<<B, 128>>>(u, r, emb, bh, hrw, hbw, trw, tbw);
    matvec_kernel<<<B, 256>>>(v, emb, bt, out, N);
}